// round 1
// baseline (speedup 1.0000x reference)
#include <cuda_runtime.h>
#include <math.h>

#define HW   128
#define HW2  (128*128)
#define NCH  32
#define NB   8
#define NT   16

// State + scratch (alloc-free: __device__ globals)
__device__ float g_h0[NB*NCH*HW2];
__device__ float g_h1[NB*NCH*HW2];
__device__ float g_rh[NB*NCH*HW2];
__device__ float g_z [NB*NCH*HW2];

__global__ void zero_states_kernel() {
    size_t i = (size_t)blockIdx.x * blockDim.x + threadIdx.x;
    float4 z = make_float4(0.f, 0.f, 0.f, 0.f);
    ((float4*)g_h0)[i] = z;
    ((float4*)g_h1)[i] = z;
}

__device__ __forceinline__ float sigmoidf_(float v) {
    return 1.0f / (1.0f + __expf(-v));
}

// One ConvGRU half-cell.
// GATES=true : conv([x, in2=h], w)+b -> sigmoid -> r (ch 0..31), z (ch 32..63)
//              out1[rh] = r * hstate ; out2[z] = z          (COUT=64)
// GATES=false: conv([x, in2=rh], w)+b -> tanh = n
//              out1[hout] = (1-z)*hstate + z*n ; out2 = z (read)   (COUT=32)
template<int CINX, bool GATES>
__global__ __launch_bounds__(256, 2)
void cell_kernel(const float* __restrict__ x, long long x_bs,
                 const float* __restrict__ in2,
                 const float* __restrict__ w,
                 const float* __restrict__ bias,
                 const float* __restrict__ hstate,
                 float* __restrict__ out1,
                 float* __restrict__ out2)
{
    constexpr int CIN  = CINX + 32;
    constexpr int COUT = GATES ? 64 : 32;
    constexpr int CPT  = COUT / 4;        // couts per thread (z-group)

    __shared__ float s_x[10 * 34];        // 8x32 tile + halo
    __shared__ float s_w[COUT * 9];       // weights for current cin

    const int tid = threadIdx.x;
    const int tz  = tid >> 6;             // 0..3  cout group
    const int ty  = (tid >> 3) & 7;       // 0..7  row in tile
    const int tx  = tid & 7;              // 0..7  4-pixel strip
    const int b    = blockIdx.z;
    const int row0 = blockIdx.y * 8;
    const int col0 = blockIdx.x * 32;
    const int row  = row0 + ty;
    const int col  = col0 + tx * 4;

    float acc[CPT][4];
    #pragma unroll
    for (int c = 0; c < CPT; c++)
        #pragma unroll
        for (int p = 0; p < 4; p++) acc[c][p] = 0.f;

    for (int cin = 0; cin < CIN; ++cin) {
        const float* plane = (cin < CINX)
            ? x   + (size_t)b * x_bs + (size_t)cin * HW2
            : in2 + ((size_t)b * 32 + (size_t)(cin - CINX)) * HW2;

        // Stage input tile with halo (zero-padded SAME)
        for (int i = tid; i < 340; i += 256) {
            int r  = i / 34, c2 = i % 34;
            int gr = row0 + r - 1, gc = col0 + c2 - 1;
            float v = 0.f;
            if (gr >= 0 && gr < HW && gc >= 0 && gc < HW)
                v = plane[gr * HW + gc];
            s_x[i] = v;
        }
        // Stage weights for this cin: w[cout][cin][3][3]
        for (int i = tid; i < COUT * 9; i += 256) {
            int co = i / 9, k = i % 9;
            s_w[i] = w[((size_t)co * CIN + cin) * 9 + k];
        }
        __syncthreads();

        float xv[3][6];
        #pragma unroll
        for (int dy = 0; dy < 3; dy++)
            #pragma unroll
            for (int j = 0; j < 6; j++)
                xv[dy][j] = s_x[(ty + dy) * 34 + tx * 4 + j];

        #pragma unroll
        for (int k = 0; k < 9; k++) {
            const int dy = k / 3, dx = k % 3;
            #pragma unroll
            for (int c = 0; c < CPT; c++) {
                float wv = s_w[(tz * CPT + c) * 9 + k];
                #pragma unroll
                for (int p = 0; p < 4; p++)
                    acc[c][p] = fmaf(xv[dy][dx + p], wv, acc[c][p]);
            }
        }
        __syncthreads();
    }

    const size_t pixoff = (size_t)row * HW + col;

    if (GATES) {
        #pragma unroll
        for (int c = 0; c < CPT; c++) {
            const int co = tz * CPT + c;
            const float bv = bias[co];
            float g0 = sigmoidf_(acc[c][0] + bv);
            float g1 = sigmoidf_(acc[c][1] + bv);
            float g2 = sigmoidf_(acc[c][2] + bv);
            float g3 = sigmoidf_(acc[c][3] + bv);
            if (co < 32) {  // r gate -> rh = r * h
                size_t off = ((size_t)b * 32 + co) * HW2 + pixoff;
                float4 hv = *(const float4*)(hstate + off);
                float4 o = make_float4(g0 * hv.x, g1 * hv.y, g2 * hv.z, g3 * hv.w);
                *(float4*)(out1 + off) = o;
            } else {        // z gate
                size_t off = ((size_t)b * 32 + (co - 32)) * HW2 + pixoff;
                *(float4*)(out2 + off) = make_float4(g0, g1, g2, g3);
            }
        }
    } else {
        #pragma unroll
        for (int c = 0; c < CPT; c++) {
            const int co = tz * CPT + c;
            const float bv = bias[co];
            size_t off = ((size_t)b * 32 + co) * HW2 + pixoff;
            float4 zv = *(const float4*)(out2 + off);
            float4 hv = *(const float4*)(hstate + off);
            float n0 = tanhf(acc[c][0] + bv);
            float n1 = tanhf(acc[c][1] + bv);
            float n2 = tanhf(acc[c][2] + bv);
            float n3 = tanhf(acc[c][3] + bv);
            float4 o;
            o.x = hv.x + zv.x * (n0 - hv.x);
            o.y = hv.y + zv.y * (n1 - hv.y);
            o.z = hv.z + zv.z * (n2 - hv.z);
            o.w = hv.w + zv.w * (n3 - hv.w);
            *(float4*)(out1 + off) = o;
        }
    }
}

extern "C" void kernel_launch(void* const* d_in, const int* in_sizes, int n_in,
                              void* d_out, int out_size)
{
    const float* seq = (const float*)d_in[0];
    const float* gw0 = (const float*)d_in[1];
    const float* gb0 = (const float*)d_in[2];
    const float* cw0 = (const float*)d_in[3];
    const float* cb0 = (const float*)d_in[4];
    const float* gw1 = (const float*)d_in[5];
    const float* gb1 = (const float*)d_in[6];
    const float* cw1 = (const float*)d_in[7];
    const float* cb1 = (const float*)d_in[8];

    float *h0, *h1, *rh, *zb;
    cudaGetSymbolAddress((void**)&h0, g_h0);
    cudaGetSymbolAddress((void**)&h1, g_h1);
    cudaGetSymbolAddress((void**)&rh, g_rh);
    cudaGetSymbolAddress((void**)&zb, g_z);

    zero_states_kernel<<<4096, 256>>>();

    dim3 grid(HW / 32, HW / 8, NB);  // (4, 16, 8)
    dim3 blk(256);
    const long long seq_bs = (long long)NT * HW2;  // batch stride in seq
    const long long h_bs   = (long long)NCH * HW2;

    for (int t = 0; t < NT; t++) {
        const float* xt = seq + (size_t)t * HW2;
        // Layer 0: x = seq[:, t] (1 ch), h = h0
        cell_kernel<1, true ><<<grid, blk>>>(xt, seq_bs, h0, gw0, gb0, h0, rh, zb);
        cell_kernel<1, false><<<grid, blk>>>(xt, seq_bs, rh, cw0, cb0, h0, h0, zb);
        // Layer 1: x = h0 (32 ch), h = h1
        cell_kernel<32, true ><<<grid, blk>>>(h0, h_bs, h1, gw1, gb1, h1, rh, zb);
        float* hout = (t == NT - 1) ? (float*)d_out : h1;
        cell_kernel<32, false><<<grid, blk>>>(h0, h_bs, rh, cw1, cb1, h1, hout, zb);
    }
}

// round 2
// speedup vs baseline: 1.0384x; 1.0384x over previous
#include <cuda_runtime.h>
#include <math.h>

#define HW   128
#define HW2  (128*128)
#define NCH  32
#define NB   8
#define NT   16
#define XSTR 35          // padded x-tile row stride (conflict-free)
#define CHUNK 4          // cin channels staged per barrier

// State + scratch (alloc-free: __device__ globals)
__device__ float g_h0[NB*NCH*HW2];
__device__ float g_h1[NB*NCH*HW2];
__device__ float g_rh[NB*NCH*HW2];
__device__ float g_z [NB*NCH*HW2];

__global__ void zero_states_kernel() {
    size_t i = (size_t)blockIdx.x * blockDim.x + threadIdx.x;
    float4 z = make_float4(0.f, 0.f, 0.f, 0.f);
    ((float4*)g_h0)[i] = z;
    ((float4*)g_h1)[i] = z;
}

__device__ __forceinline__ float sigmoidf_(float v) {
    return 1.0f / (1.0f + __expf(-v));
}

typedef unsigned long long u64;

__device__ __forceinline__ u64 fma2(u64 a, u64 b, u64 c) {
    u64 d;
    asm("fma.rn.f32x2 %0, %1, %2, %3;" : "=l"(d) : "l"(a), "l"(b), "l"(c));
    return d;
}
__device__ __forceinline__ u64 pack2(float lo, float hi) {
    u64 d;
    asm("mov.b64 %0, {%1, %2};" : "=l"(d) : "f"(lo), "f"(hi));
    return d;
}
__device__ __forceinline__ void unpack2(u64 v, float& lo, float& hi) {
    asm("mov.b64 {%0, %1}, %2;" : "=f"(lo), "=f"(hi) : "l"(v));
}

// One ConvGRU half-cell (see R1 comment for semantics).
template<int CINX, bool GATES>
__global__ __launch_bounds__(256, 2)
void cell_kernel(const float* __restrict__ x, long long x_bs,
                 const float* __restrict__ in2,
                 const float* __restrict__ w,
                 const float* __restrict__ bias,
                 const float* __restrict__ hstate,
                 float* __restrict__ out1,
                 float* __restrict__ out2)
{
    constexpr int CIN  = CINX + 32;
    constexpr int COUT = GATES ? 64 : 32;
    constexpr int CPT  = COUT / 4;        // couts per thread (z-group)

    __shared__ float  s_x[CHUNK][10 * XSTR];   // 8x32 tile + halo, per staged cin
    __shared__ float2 s_w2[CHUNK * COUT * 9];  // duplicated weights

    const int tid = threadIdx.x;
    const int tz  = tid >> 6;             // 0..3  cout group
    const int ty  = (tid >> 3) & 7;       // 0..7  row in tile
    const int tx  = tid & 7;              // 0..7  4-pixel strip
    const int b    = blockIdx.z;
    const int row0 = blockIdx.y * 8;
    const int col0 = blockIdx.x * 32;
    const int row  = row0 + ty;
    const int col  = col0 + tx * 4;

    u64 acc[CPT][2];
    #pragma unroll
    for (int c = 0; c < CPT; c++) { acc[c][0] = 0ull; acc[c][1] = 0ull; }

    for (int cin0 = 0; cin0 < CIN; cin0 += CHUNK) {
        const int nc = (CIN - cin0 < CHUNK) ? (CIN - cin0) : CHUNK;

        // Stage nc input tiles with halo (zero-padded SAME)
        for (int i = tid; i < nc * 340; i += 256) {
            const int pl  = i / 340;
            const int rem = i - pl * 340;
            const int r   = rem / 34, c2 = rem - (rem / 34) * 34;
            const int cin = cin0 + pl;
            const float* plane = (cin < CINX)
                ? x   + (size_t)b * x_bs + (size_t)cin * HW2
                : in2 + ((size_t)b * 32 + (size_t)(cin - CINX)) * HW2;
            const int gr = row0 + r - 1, gc = col0 + c2 - 1;
            float v = 0.f;
            if (gr >= 0 && gr < HW && gc >= 0 && gc < HW)
                v = plane[gr * HW + gc];
            s_x[pl][r * XSTR + c2] = v;
        }
        // Stage duplicated weights: w[cout][cin][3][3] -> s_w2[pl*COUT*9 + co*9 + k]
        for (int i = tid; i < nc * COUT * 9; i += 256) {
            const int pl  = i / (COUT * 9);
            const int rem = i - pl * (COUT * 9);
            const int co  = rem / 9, k = rem - co * 9;
            const float wv = w[((size_t)co * CIN + cin0 + pl) * 9 + k];
            s_w2[i] = make_float2(wv, wv);
        }
        __syncthreads();

        #pragma unroll
        for (int pl = 0; pl < CHUNK; pl++) {
            if (pl < nc) {
                // Build 5 overlapping packed pairs per row
                u64 xp[3][5];
                #pragma unroll
                for (int dy = 0; dy < 3; dy++) {
                    float xs[6];
                    #pragma unroll
                    for (int j = 0; j < 6; j++)
                        xs[j] = s_x[pl][(ty + dy) * XSTR + tx * 4 + j];
                    #pragma unroll
                    for (int m = 0; m < 5; m++)
                        xp[dy][m] = pack2(xs[m], xs[m + 1]);
                }

                const u64* wrow = (const u64*)(s_w2 + (pl * COUT + tz * CPT) * 9);
                #pragma unroll
                for (int k = 0; k < 9; k++) {
                    const int dy = k / 3, dx = k % 3;
                    #pragma unroll
                    for (int c = 0; c < CPT; c++) {
                        u64 wp = wrow[c * 9 + k];          // LDS.64, warp-broadcast
                        acc[c][0] = fma2(xp[dy][dx],     wp, acc[c][0]);
                        acc[c][1] = fma2(xp[dy][dx + 2], wp, acc[c][1]);
                    }
                }
            }
        }
        __syncthreads();
    }

    const size_t pixoff = (size_t)row * HW + col;

    if (GATES) {
        #pragma unroll
        for (int c = 0; c < CPT; c++) {
            const int co = tz * CPT + c;
            const float bv = bias[co];
            float a0, a1, a2, a3;
            unpack2(acc[c][0], a0, a1);
            unpack2(acc[c][1], a2, a3);
            float g0 = sigmoidf_(a0 + bv);
            float g1 = sigmoidf_(a1 + bv);
            float g2 = sigmoidf_(a2 + bv);
            float g3 = sigmoidf_(a3 + bv);
            if (co < 32) {  // r gate -> rh = r * h
                size_t off = ((size_t)b * 32 + co) * HW2 + pixoff;
                float4 hv = *(const float4*)(hstate + off);
                float4 o = make_float4(g0 * hv.x, g1 * hv.y, g2 * hv.z, g3 * hv.w);
                *(float4*)(out1 + off) = o;
            } else {        // z gate
                size_t off = ((size_t)b * 32 + (co - 32)) * HW2 + pixoff;
                *(float4*)(out2 + off) = make_float4(g0, g1, g2, g3);
            }
        }
    } else {
        #pragma unroll
        for (int c = 0; c < CPT; c++) {
            const int co = tz * CPT + c;
            const float bv = bias[co];
            size_t off = ((size_t)b * 32 + co) * HW2 + pixoff;
            float4 zv = *(const float4*)(out2 + off);
            float4 hv = *(const float4*)(hstate + off);
            float a0, a1, a2, a3;
            unpack2(acc[c][0], a0, a1);
            unpack2(acc[c][1], a2, a3);
            float n0 = tanhf(a0 + bv);
            float n1 = tanhf(a1 + bv);
            float n2 = tanhf(a2 + bv);
            float n3 = tanhf(a3 + bv);
            float4 o;
            o.x = hv.x + zv.x * (n0 - hv.x);
            o.y = hv.y + zv.y * (n1 - hv.y);
            o.z = hv.z + zv.z * (n2 - hv.z);
            o.w = hv.w + zv.w * (n3 - hv.w);
            *(float4*)(out1 + off) = o;
        }
    }
}

extern "C" void kernel_launch(void* const* d_in, const int* in_sizes, int n_in,
                              void* d_out, int out_size)
{
    const float* seq = (const float*)d_in[0];
    const float* gw0 = (const float*)d_in[1];
    const float* gb0 = (const float*)d_in[2];
    const float* cw0 = (const float*)d_in[3];
    const float* cb0 = (const float*)d_in[4];
    const float* gw1 = (const float*)d_in[5];
    const float* gb1 = (const float*)d_in[6];
    const float* cw1 = (const float*)d_in[7];
    const float* cb1 = (const float*)d_in[8];

    float *h0, *h1, *rh, *zb;
    cudaGetSymbolAddress((void**)&h0, g_h0);
    cudaGetSymbolAddress((void**)&h1, g_h1);
    cudaGetSymbolAddress((void**)&rh, g_rh);
    cudaGetSymbolAddress((void**)&zb, g_z);

    zero_states_kernel<<<4096, 256>>>();

    dim3 grid(HW / 32, HW / 8, NB);  // (4, 16, 8)
    dim3 blk(256);
    const long long seq_bs = (long long)NT * HW2;  // batch stride in seq
    const long long h_bs   = (long long)NCH * HW2;

    for (int t = 0; t < NT; t++) {
        const float* xt = seq + (size_t)t * HW2;
        // Layer 0: x = seq[:, t] (1 ch), h = h0
        cell_kernel<1, true ><<<grid, blk>>>(xt, seq_bs, h0, gw0, gb0, h0, rh, zb);
        cell_kernel<1, false><<<grid, blk>>>(xt, seq_bs, rh, cw0, cb0, h0, h0, zb);
        // Layer 1: x = h0 (32 ch), h = h1
        cell_kernel<32, true ><<<grid, blk>>>(h0, h_bs, h1, gw1, gb1, h1, rh, zb);
        float* hout = (t == NT - 1) ? (float*)d_out : h1;
        cell_kernel<32, false><<<grid, blk>>>(h0, h_bs, rh, cw1, cb1, h1, hout, zb);
    }
}

// round 3
// speedup vs baseline: 1.6943x; 1.6316x over previous
#include <cuda_runtime.h>
#include <math.h>

#define HW   128
#define HW2  (128*128)
#define NB   8
#define NT   16

typedef unsigned int uint;

// State + scratch (alloc-free: __device__ globals)
__device__ float g_h0[NB*32*HW2];
__device__ float g_h1[NB*32*HW2];
__device__ float g_rh[NB*32*HW2];
__device__ float g_z [NB*32*HW2];

__global__ void zero_states_kernel() {
    size_t i = (size_t)blockIdx.x * blockDim.x + threadIdx.x;
    float4 z = make_float4(0.f, 0.f, 0.f, 0.f);
    ((float4*)g_h0)[i] = z;
    ((float4*)g_h1)[i] = z;
}

__device__ __forceinline__ float sigf(float v) {
    return 1.0f / (1.0f + __expf(-v));
}
__device__ __forceinline__ float tanhfast(float v) {
    return 1.0f - 2.0f / (__expf(2.0f * v) + 1.0f);
}
__device__ __forceinline__ uint tf32r(float f) {
    uint u;
    asm("cvt.rna.tf32.f32 %0, %1;" : "=r"(u) : "f"(f));
    return u;
}
__device__ __forceinline__ void mma8(float* c, uint a0, uint a1, uint a2, uint a3,
                                     uint b0, uint b1) {
    asm volatile(
        "mma.sync.aligned.m16n8k8.row.col.f32.tf32.tf32.f32 "
        "{%0,%1,%2,%3},{%4,%5,%6,%7},{%8,%9},{%0,%1,%2,%3};"
        : "+f"(c[0]), "+f"(c[1]), "+f"(c[2]), "+f"(c[3])
        : "r"(a0), "r"(a1), "r"(a2), "r"(a3), "r"(b0), "r"(b1));
}

// Implicit-GEMM ConvGRU half-cell on tensor cores (tf32).
// Pixel tile: 32x8 per CTA; K = (XP + 32) input planes x 9 taps.
// XP=8 : layer0 (plane0 = x, planes 1..7 zero), weight cin = {0} U {1..32}
// XP=32: layer1 (planes 0..31 = x=h0), weight cin = 0..63
// GATES: sigmoid -> rh (co<32), z (co>=32).  !GATES: tanh -> h update.
template<int COUT, int XP, bool GATES>
__global__ __launch_bounds__(256, 2)
void cell_mma(const float* __restrict__ x, long long x_bs,
              const float* __restrict__ in2,
              const float* __restrict__ w,
              const float* __restrict__ bias,
              const float* __restrict__ hstate,
              float* __restrict__ out1,
              float* __restrict__ out2)
{
    constexpr int KTOT  = XP + 32;
    constexpr int CIN_W = (XP == 8) ? 33 : 64;
    constexpr int KT8   = KTOT / 8;
    constexpr int NGRP  = (COUT == 64) ? 4 : 8;   // warps along N
    constexpr int RPW   = 8 / NGRP;               // pixel rows per warp
    constexpr int N8    = RPW * 4;                // n8-tiles per warp
    constexpr int MT    = 2;                      // m16 tiles per warp (M=32)

    extern __shared__ uint smu[];
    uint* Xs  = smu;                 // [KTOT][10][36] tf32
    uint* Wsm = smu + KTOT * 360;    // [KTOT][72]     tf32 (per tap)

    const int tid  = threadIdx.x;
    const int lane = tid & 31;
    const int wid  = tid >> 5;
    const int lq   = lane >> 2;      // 0..7
    const int lr   = lane & 3;       // 0..3
    const int nwarp = wid & (NGRP - 1);
    const int mwarp = wid / NGRP;
    const int pyw   = nwarp * RPW;

    const int b    = blockIdx.z;
    const int row0 = blockIdx.y * 8;
    const int col0 = blockIdx.x * 32;

    // ---- Stage X planes (with zero halo), tf32-rounded ----
    for (int i = tid; i < KTOT * 340; i += 256) {
        const int pl  = i / 340;
        const int rem = i - pl * 340;
        const int yy  = rem / 34;
        const int xx  = rem - yy * 34;
        const int gr = row0 + yy - 1, gc = col0 + xx - 1;
        float v = 0.f;
        const bool inb = (gr >= 0 && gr < HW && gc >= 0 && gc < HW);
        if (XP == 8) {
            if (pl == 0) { if (inb) v = x[(size_t)b * x_bs + gr * HW + gc]; }
            else if (pl >= 8) { if (inb) v = in2[((size_t)b * 32 + pl - 8) * HW2 + gr * HW + gc]; }
        } else {
            if (pl < 32) { if (inb) v = x[(size_t)b * x_bs + (size_t)pl * HW2 + gr * HW + gc]; }
            else         { if (inb) v = in2[((size_t)b * 32 + pl - 32) * HW2 + gr * HW + gc]; }
        }
        Xs[pl * 360 + yy * 36 + xx] = tf32r(v);
    }
    __syncthreads();

    float acc[MT][N8][4];
    #pragma unroll
    for (int mt = 0; mt < MT; mt++)
        #pragma unroll
        for (int j = 0; j < N8; j++)
            #pragma unroll
            for (int q = 0; q < 4; q++) acc[mt][j][q] = 0.f;

    // ---- Tap loop: stage W[tap] then MMA over all k-slices ----
    for (int tap = 0; tap < 9; tap++) {
        const int dy = tap / 3, dx = tap - dy * 3;

        if (tap) __syncthreads();   // protect Wsm reuse
        for (int i = tid; i < KTOT * COUT; i += 256) {
            const int r  = i / COUT;
            const int co = i - r * COUT;
            float v = 0.f;
            int cw;
            if (XP == 8) cw = (r == 0) ? 0 : ((r >= 8) ? r - 7 : -1);
            else         cw = r;
            if (cw >= 0) v = w[((size_t)co * CIN_W + cw) * 9 + tap];
            Wsm[r * 72 + co] = tf32r(v);
        }
        __syncthreads();

        #pragma unroll
        for (int ks = 0; ks < KT8; ks++) {
            const uint* xb = Xs + (ks * 8 + lr) * 360 + dy * 36 + dx + lq;
            uint bf[N8][2];
            #pragma unroll
            for (int j = 0; j < N8; j++) {
                const uint* p = xb + (pyw + (j >> 2)) * 36 + (j & 3) * 8;
                bf[j][0] = p[0];
                bf[j][1] = p[4 * 360];
            }
            #pragma unroll
            for (int mt = 0; mt < MT; mt++) {
                const uint* wb = Wsm + (ks * 8 + lr) * 72 + mwarp * 32 + mt * 16 + lq;
                const uint a0 = wb[0], a1 = wb[8];
                const uint a2 = wb[4 * 72], a3 = wb[4 * 72 + 8];
                #pragma unroll
                for (int j = 0; j < N8; j++)
                    mma8(acc[mt][j], a0, a1, a2, a3, bf[j][0], bf[j][1]);
            }
        }
    }

    // ---- Epilogue ----
    #pragma unroll
    for (int mt = 0; mt < MT; mt++) {
        #pragma unroll
        for (int j = 0; j < N8; j++) {
            const int py = row0 + pyw + (j >> 2);
            const int px = col0 + (j & 3) * 8 + 2 * lr;
            const size_t pix = (size_t)py * HW + px;
            #pragma unroll
            for (int h2 = 0; h2 < 2; h2++) {
                const int cc = mwarp * 32 + mt * 16 + lq + h2 * 8;
                const float bv = __ldg(bias + cc);
                float v0 = acc[mt][j][h2 * 2 + 0] + bv;
                float v1 = acc[mt][j][h2 * 2 + 1] + bv;
                if (GATES) {
                    const float g0 = sigf(v0), g1 = sigf(v1);
                    if (mwarp == 0) {   // r gate -> rh = r*h
                        const size_t off = ((size_t)b * 32 + cc) * HW2 + pix;
                        const float2 hv = *(const float2*)(hstate + off);
                        *(float2*)(out1 + off) = make_float2(g0 * hv.x, g1 * hv.y);
                    } else {            // z gate
                        const size_t off = ((size_t)b * 32 + cc - 32) * HW2 + pix;
                        *(float2*)(out2 + off) = make_float2(g0, g1);
                    }
                } else {
                    const size_t off = ((size_t)b * 32 + cc) * HW2 + pix;
                    const float2 zv = *(const float2*)(out2 + off);
                    const float2 hv = *(const float2*)(hstate + off);
                    const float n0 = tanhfast(v0), n1 = tanhfast(v1);
                    *(float2*)(out1 + off) =
                        make_float2(hv.x + zv.x * (n0 - hv.x),
                                    hv.y + zv.y * (n1 - hv.y));
                }
            }
        }
    }
}

extern "C" void kernel_launch(void* const* d_in, const int* in_sizes, int n_in,
                              void* d_out, int out_size)
{
    const float* seq = (const float*)d_in[0];
    const float* gw0 = (const float*)d_in[1];
    const float* gb0 = (const float*)d_in[2];
    const float* cw0 = (const float*)d_in[3];
    const float* cb0 = (const float*)d_in[4];
    const float* gw1 = (const float*)d_in[5];
    const float* gb1 = (const float*)d_in[6];
    const float* cw1 = (const float*)d_in[7];
    const float* cb1 = (const float*)d_in[8];

    float *h0, *h1, *rh, *zb;
    cudaGetSymbolAddress((void**)&h0, g_h0);
    cudaGetSymbolAddress((void**)&h1, g_h1);
    cudaGetSymbolAddress((void**)&rh, g_rh);
    cudaGetSymbolAddress((void**)&zb, g_z);

    const int SM0 = 40 * 432 * 4;   // layer0 smem (69120 B)
    const int SM1 = 64 * 432 * 4;   // layer1 smem (110592 B)
    cudaFuncSetAttribute(cell_mma<64, 8,  true >, cudaFuncAttributeMaxDynamicSharedMemorySize, SM0);
    cudaFuncSetAttribute(cell_mma<32, 8,  false>, cudaFuncAttributeMaxDynamicSharedMemorySize, SM0);
    cudaFuncSetAttribute(cell_mma<64, 32, true >, cudaFuncAttributeMaxDynamicSharedMemorySize, SM1);
    cudaFuncSetAttribute(cell_mma<32, 32, false>, cudaFuncAttributeMaxDynamicSharedMemorySize, SM1);

    zero_states_kernel<<<4096, 256>>>();

    dim3 grid(HW / 32, HW / 8, NB);  // (4, 16, 8)
    dim3 blk(256);
    const long long seq_bs = (long long)NT * HW2;  // batch stride in seq
    const long long h_bs   = (long long)32 * HW2;

    for (int t = 0; t < NT; t++) {
        const float* xt = seq + (size_t)t * HW2;
        // Layer 0
        cell_mma<64, 8,  true ><<<grid, blk, SM0>>>(xt, seq_bs, h0, gw0, gb0, h0, rh, zb);
        cell_mma<32, 8,  false><<<grid, blk, SM0>>>(xt, seq_bs, rh, cw0, cb0, h0, h0, zb);
        // Layer 1
        cell_mma<64, 32, true ><<<grid, blk, SM1>>>(h0, h_bs, h1, gw1, gb1, h1, rh, zb);
        float* hout = (t == NT - 1) ? (float*)d_out : h1;
        cell_mma<32, 32, false><<<grid, blk, SM1>>>(h0, h_bs, rh, cw1, cb1, h1, hout, zb);
    }
}

// round 4
// speedup vs baseline: 2.8509x; 1.6826x over previous
#include <cuda_runtime.h>
#include <math.h>

#define HW   128
#define HW2  (128*128)
#define NB   8
#define NT   16

typedef unsigned int uint;

// State + scratch (alloc-free: __device__ globals)
__device__ float g_h0[NB*32*HW2];
__device__ float g_h1[NB*32*HW2];
__device__ float g_rh[NB*32*HW2];
__device__ float g_z [NB*32*HW2];

// Pre-swizzled weight fragments (tf32, MMA A-operand layout, uint4 per lane)
__device__ uint4 g_wf_g0[9 * 5 * 2 * 2 * 32];   // layer0 gates : KT8=5, MW=2
__device__ uint4 g_wf_c0[9 * 5 * 1 * 2 * 32];   // layer0 cand  : KT8=5, MW=1
__device__ uint4 g_wf_g1[9 * 8 * 2 * 2 * 32];   // layer1 gates : KT8=8, MW=2
__device__ uint4 g_wf_c1[9 * 8 * 1 * 2 * 32];   // layer1 cand  : KT8=8, MW=1

__global__ void zero_states_kernel() {
    size_t i = (size_t)blockIdx.x * blockDim.x + threadIdx.x;
    float4 z = make_float4(0.f, 0.f, 0.f, 0.f);
    ((float4*)g_h0)[i] = z;
    ((float4*)g_h1)[i] = z;
}

__device__ __forceinline__ float sigf(float v) {
    return 1.0f / (1.0f + __expf(-v));
}
__device__ __forceinline__ float tanhfast(float v) {
    return 1.0f - 2.0f / (__expf(2.0f * v) + 1.0f);
}
__device__ __forceinline__ uint tf32r(float f) {
    uint u;
    asm("cvt.rna.tf32.f32 %0, %1;" : "=r"(u) : "f"(f));
    return u;
}
__device__ __forceinline__ void mma8(float* c, uint a0, uint a1, uint a2, uint a3,
                                     uint b0, uint b1) {
    asm volatile(
        "mma.sync.aligned.m16n8k8.row.col.f32.tf32.tf32.f32 "
        "{%0,%1,%2,%3},{%4,%5,%6,%7},{%8,%9},{%0,%1,%2,%3};"
        : "+f"(c[0]), "+f"(c[1]), "+f"(c[2]), "+f"(c[3])
        : "r"(a0), "r"(a1), "r"(a2), "r"(a3), "r"(b0), "r"(b1));
}

// Weight fragment prep: one uint4 per (tap, ks, mw, mt, lane).
// Main-loop fragment semantics (row=cout, col=k):
//   a0=W[k0][co0]  a1=W[k0][co0+8]  a2=W[k0+4][co0]  a3=W[k0+4][co0+8]
//   k0 = ks*8 + (lane&3), co0 = mw*32 + mt*16 + (lane>>2)
// cin mapping (virtual plane k -> weight cin): L0: k=0->0, 8<=k<40 -> k-7, else pad0
//                                              L1: k -> k
template<int KTOT, int COUT, int CIN_W, bool L0>
__global__ void prep_w(const float* __restrict__ w, uint4* __restrict__ out) {
    constexpr int KT8 = KTOT / 8;
    constexpr int MW  = COUT / 32;
    const int total = 9 * KT8 * MW * 2 * 32;
    int idx = blockIdx.x * blockDim.x + threadIdx.x;
    if (idx >= total) return;
    int t = idx;
    const int lane = t & 31; t >>= 5;
    const int mt = t & 1; t >>= 1;
    const int mw = t % MW; t /= MW;
    const int ks = t % KT8;
    const int tap = t / KT8;

    const int k0  = ks * 8 + (lane & 3);
    const int co0 = mw * 32 + mt * 16 + (lane >> 2);

    auto Wv = [&](int k, int co) -> float {
        int cw;
        if (L0) cw = (k == 0) ? 0 : ((k >= 8 && k < 40) ? k - 7 : -1);
        else    cw = k;
        if (cw < 0) return 0.f;
        return w[((size_t)co * CIN_W + cw) * 9 + tap];
    };
    uint4 o;
    o.x = tf32r(Wv(k0,     co0));
    o.y = tf32r(Wv(k0,     co0 + 8));
    o.z = tf32r(Wv(k0 + 4, co0));
    o.w = tf32r(Wv(k0 + 4, co0 + 8));
    out[idx] = o;
}

// Implicit-GEMM ConvGRU half-cell on tensor cores (tf32).
// Pixel tile: 32x8 per CTA; K = (XP + 32) virtual input planes x 9 taps.
template<int COUT, int XP, bool GATES>
__global__ __launch_bounds__(256, 2)
void cell_mma(const float* __restrict__ x, long long x_bs,
              const float* __restrict__ in2,
              const uint4* __restrict__ wf,
              const float* __restrict__ bias,
              const float* __restrict__ hstate,
              float* __restrict__ out1,
              float* __restrict__ out2)
{
    constexpr int KTOT  = XP + 32;
    constexpr int KT8   = KTOT / 8;
    constexpr int MW    = COUT / 32;
    constexpr int NGRP  = (COUT == 64) ? 4 : 8;   // warps along N
    constexpr int RPW   = 8 / NGRP;               // pixel rows per warp
    constexpr int N8    = RPW * 4;                // n8-tiles per warp
    constexpr int MT    = 2;                      // m16 tiles per warp (M=32)

    extern __shared__ uint Xs[];     // [KTOT][10][36] tf32

    const int tid  = threadIdx.x;
    const int lane = tid & 31;
    const int wid  = tid >> 5;
    const int lq   = lane >> 2;      // 0..7
    const int lr   = lane & 3;       // 0..3
    const int nwarp = wid & (NGRP - 1);
    const int mwarp = wid / NGRP;    // 0..MW-1
    const int pyw   = nwarp * RPW;

    const int b    = blockIdx.z;
    const int row0 = blockIdx.y * 8;
    const int col0 = blockIdx.x * 32;

    // ---- Stage X planes (with zero halo), tf32-rounded ----
    for (int i = tid; i < KTOT * 340; i += 256) {
        const int pl  = i / 340;
        const int rem = i - pl * 340;
        const int yy  = rem / 34;
        const int xx  = rem - yy * 34;
        const int gr = row0 + yy - 1, gc = col0 + xx - 1;
        float v = 0.f;
        const bool inb = (gr >= 0 && gr < HW && gc >= 0 && gc < HW);
        if (XP == 8) {
            if (pl == 0) { if (inb) v = x[(size_t)b * x_bs + gr * HW + gc]; }
            else if (pl >= 8) { if (inb) v = in2[((size_t)b * 32 + pl - 8) * HW2 + gr * HW + gc]; }
        } else {
            if (pl < 32) { if (inb) v = x[(size_t)b * x_bs + (size_t)pl * HW2 + gr * HW + gc]; }
            else         { if (inb) v = in2[((size_t)b * 32 + pl - 32) * HW2 + gr * HW + gc]; }
        }
        Xs[pl * 360 + yy * 36 + xx] = tf32r(v);
    }
    __syncthreads();

    float acc[MT][N8][4];
    #pragma unroll
    for (int mt = 0; mt < MT; mt++)
        #pragma unroll
        for (int j = 0; j < N8; j++)
            #pragma unroll
            for (int q = 0; q < 4; q++) acc[mt][j][q] = 0.f;

    // ---- Main loop: taps x k-slices, weights from pre-swizzled fragments ----
    #pragma unroll 1
    for (int tap = 0; tap < 9; tap++) {
        const int dy = tap / 3, dx = tap - dy * 3;
        #pragma unroll
        for (int ks = 0; ks < KT8; ks++) {
            const uint* xb = Xs + (ks * 8 + lr) * 360 + dy * 36 + dx + lq;
            uint bf[N8][2];
            #pragma unroll
            for (int j = 0; j < N8; j++) {
                const uint* p = xb + (pyw + (j >> 2)) * 36 + (j & 3) * 8;
                bf[j][0] = p[0];
                bf[j][1] = p[4 * 360];
            }
            const uint4* wbase = wf + (((tap * KT8 + ks) * MW + mwarp) * 2) * 32 + lane;
            #pragma unroll
            for (int mt = 0; mt < MT; mt++) {
                const uint4 a = __ldg(wbase + mt * 32);
                #pragma unroll
                for (int j = 0; j < N8; j++)
                    mma8(acc[mt][j], a.x, a.y, a.z, a.w, bf[j][0], bf[j][1]);
            }
        }
    }

    // ---- Epilogue ----
    #pragma unroll
    for (int mt = 0; mt < MT; mt++) {
        #pragma unroll
        for (int j = 0; j < N8; j++) {
            const int py = row0 + pyw + (j >> 2);
            const int px = col0 + (j & 3) * 8 + 2 * lr;
            const size_t pix = (size_t)py * HW + px;
            #pragma unroll
            for (int h2 = 0; h2 < 2; h2++) {
                const int cc = mwarp * 32 + mt * 16 + lq + h2 * 8;
                const float bv = __ldg(bias + cc);
                float v0 = acc[mt][j][h2 * 2 + 0] + bv;
                float v1 = acc[mt][j][h2 * 2 + 1] + bv;
                if (GATES) {
                    const float g0 = sigf(v0), g1 = sigf(v1);
                    if (mwarp == 0) {   // r gate -> rh = r*h
                        const size_t off = ((size_t)b * 32 + cc) * HW2 + pix;
                        const float2 hv = *(const float2*)(hstate + off);
                        *(float2*)(out1 + off) = make_float2(g0 * hv.x, g1 * hv.y);
                    } else {            // z gate
                        const size_t off = ((size_t)b * 32 + cc - 32) * HW2 + pix;
                        *(float2*)(out2 + off) = make_float2(g0, g1);
                    }
                } else {
                    const size_t off = ((size_t)b * 32 + cc) * HW2 + pix;
                    const float2 zv = *(const float2*)(out2 + off);
                    const float2 hv = *(const float2*)(hstate + off);
                    const float n0 = tanhfast(v0), n1 = tanhfast(v1);
                    *(float2*)(out1 + off) =
                        make_float2(hv.x + zv.x * (n0 - hv.x),
                                    hv.y + zv.y * (n1 - hv.y));
                }
            }
        }
    }
}

extern "C" void kernel_launch(void* const* d_in, const int* in_sizes, int n_in,
                              void* d_out, int out_size)
{
    const float* seq = (const float*)d_in[0];
    const float* gw0 = (const float*)d_in[1];
    const float* gb0 = (const float*)d_in[2];
    const float* cw0 = (const float*)d_in[3];
    const float* cb0 = (const float*)d_in[4];
    const float* gw1 = (const float*)d_in[5];
    const float* gb1 = (const float*)d_in[6];
    const float* cw1 = (const float*)d_in[7];
    const float* cb1 = (const float*)d_in[8];

    float *h0, *h1, *rh, *zb;
    cudaGetSymbolAddress((void**)&h0, g_h0);
    cudaGetSymbolAddress((void**)&h1, g_h1);
    cudaGetSymbolAddress((void**)&rh, g_rh);
    cudaGetSymbolAddress((void**)&zb, g_z);
    uint4 *wfg0, *wfc0, *wfg1, *wfc1;
    cudaGetSymbolAddress((void**)&wfg0, g_wf_g0);
    cudaGetSymbolAddress((void**)&wfc0, g_wf_c0);
    cudaGetSymbolAddress((void**)&wfg1, g_wf_g1);
    cudaGetSymbolAddress((void**)&wfc1, g_wf_c1);

    const int SM0 = 40 * 360 * 4;   // layer0 smem (57600 B)
    const int SM1 = 64 * 360 * 4;   // layer1 smem (92160 B)
    cudaFuncSetAttribute(cell_mma<64, 8,  true >, cudaFuncAttributeMaxDynamicSharedMemorySize, SM0);
    cudaFuncSetAttribute(cell_mma<32, 8,  false>, cudaFuncAttributeMaxDynamicSharedMemorySize, SM0);
    cudaFuncSetAttribute(cell_mma<64, 32, true >, cudaFuncAttributeMaxDynamicSharedMemorySize, SM1);
    cudaFuncSetAttribute(cell_mma<32, 32, false>, cudaFuncAttributeMaxDynamicSharedMemorySize, SM1);

    zero_states_kernel<<<4096, 256>>>();
    prep_w<40, 64, 33, true ><<<(9*5*2*2*32 + 255)/256, 256>>>(gw0, wfg0);
    prep_w<40, 32, 33, true ><<<(9*5*1*2*32 + 255)/256, 256>>>(cw0, wfc0);
    prep_w<64, 64, 64, false><<<(9*8*2*2*32 + 255)/256, 256>>>(gw1, wfg1);
    prep_w<64, 32, 64, false><<<(9*8*1*2*32 + 255)/256, 256>>>(cw1, wfc1);

    dim3 grid(HW / 32, HW / 8, NB);  // (4, 16, 8)
    dim3 blk(256);
    const long long seq_bs = (long long)NT * HW2;  // batch stride in seq
    const long long h_bs   = (long long)32 * HW2;

    for (int t = 0; t < NT; t++) {
        const float* xt = seq + (size_t)t * HW2;
        // Layer 0
        cell_mma<64, 8,  true ><<<grid, blk, SM0>>>(xt, seq_bs, h0, wfg0, gb0, h0, rh, zb);
        cell_mma<32, 8,  false><<<grid, blk, SM0>>>(xt, seq_bs, rh, wfc0, cb0, h0, h0, zb);
        // Layer 1
        cell_mma<64, 32, true ><<<grid, blk, SM1>>>(h0, h_bs, h1, wfg1, gb1, h1, rh, zb);
        float* hout = (t == NT - 1) ? (float*)d_out : h1;
        cell_mma<32, 32, false><<<grid, blk, SM1>>>(h0, h_bs, rh, wfc1, cb1, h1, hout, zb);
    }
}

// round 5
// speedup vs baseline: 4.4389x; 1.5570x over previous
#include <cuda_runtime.h>
#include <cuda_fp16.h>
#include <math.h>

#define HW   128
#define HW2  (128*128)
#define NB   8
#define NT   16

typedef unsigned int uint;

// State + scratch (alloc-free: __device__ globals)
__device__ float g_h0[NB*32*HW2];
__device__ float g_h1[NB*32*HW2];
__device__ float g_rh[NB*32*HW2];
__device__ float g_z [NB*32*HW2];

// Pre-swizzled weight fragments (f16x2, MMA m16n8k16 A layout, uint4 per lane)
// Layer0: KTOT=48 (KT16=3), Layer1: KTOT=64 (KT16=4)
__device__ uint4 g_wf_g0[9 * 3 * 2 * 2 * 32];
__device__ uint4 g_wf_c0[9 * 3 * 1 * 2 * 32];
__device__ uint4 g_wf_g1[9 * 4 * 2 * 2 * 32];
__device__ uint4 g_wf_c1[9 * 4 * 1 * 2 * 32];

__global__ void zero_states_kernel() {
    size_t i = (size_t)blockIdx.x * blockDim.x + threadIdx.x;
    float4 z = make_float4(0.f, 0.f, 0.f, 0.f);
    ((float4*)g_h0)[i] = z;
    ((float4*)g_h1)[i] = z;
}

__device__ __forceinline__ float sigf(float v) {
    return 1.0f / (1.0f + __expf(-v));
}
__device__ __forceinline__ float tanhfast(float v) {
    return 1.0f - 2.0f / (__expf(2.0f * v) + 1.0f);
}
__device__ __forceinline__ uint h2u(float lo, float hi) {
    __half2 h = __halves2half2(__float2half_rn(lo), __float2half_rn(hi));
    return *(uint*)&h;
}
__device__ __forceinline__ void mma16(float* c, uint a0, uint a1, uint a2, uint a3,
                                      uint b0, uint b1) {
    asm volatile(
        "mma.sync.aligned.m16n8k16.row.col.f32.f16.f16.f32 "
        "{%0,%1,%2,%3},{%4,%5,%6,%7},{%8,%9},{%0,%1,%2,%3};"
        : "+f"(c[0]), "+f"(c[1]), "+f"(c[2]), "+f"(c[3])
        : "r"(a0), "r"(a1), "r"(a2), "r"(a3), "r"(b0), "r"(b1));
}

// Virtual plane k -> weight cin. L0: k==0 -> 0 (x), 16<=k<48 -> k-15 (h), else pad0.
// L1: k -> k (0..31 = x=h0, 32..63 = h/rh).
// A fragment (m16n8k16): co0 = mw*32+mt*16+(lane>>2), r = lane&3, kb = ks*16.
//   a0={W(co0,kb+2r),W(co0,kb+2r+1)}  a1={W(co0+8,..)}  a2={W(co0,kb+2r+8..)}  a3={W(co0+8,kb+2r+8..)}
template<int KTOT, int COUT, int CIN_W, bool L0>
__global__ void prep_w(const float* __restrict__ w, uint4* __restrict__ out) {
    constexpr int KT16 = KTOT / 16;
    constexpr int MW   = COUT / 32;
    const int total = 9 * KT16 * MW * 2 * 32;
    int idx = blockIdx.x * blockDim.x + threadIdx.x;
    if (idx >= total) return;
    int t = idx;
    const int lane = t & 31; t >>= 5;
    const int mt = t & 1; t >>= 1;
    const int mw = t % MW; t /= MW;
    const int ks = t % KT16;
    const int tap = t / KT16;

    const int co0 = mw * 32 + mt * 16 + (lane >> 2);
    const int kb  = ks * 16 + (lane & 3) * 2;

    auto Wv = [&](int co, int k) -> float {
        int cw;
        if (L0) cw = (k == 0) ? 0 : ((k >= 16 && k < 48) ? k - 15 : -1);
        else    cw = k;
        if (cw < 0) return 0.f;
        return w[((size_t)co * CIN_W + cw) * 9 + tap];
    };
    uint4 o;
    o.x = h2u(Wv(co0,     kb),     Wv(co0,     kb + 1));
    o.y = h2u(Wv(co0 + 8, kb),     Wv(co0 + 8, kb + 1));
    o.z = h2u(Wv(co0,     kb + 8), Wv(co0,     kb + 9));
    o.w = h2u(Wv(co0 + 8, kb + 8), Wv(co0 + 8, kb + 9));
    out[idx] = o;
}

// Implicit-GEMM ConvGRU half-cell, fp16 tensor cores (m16n8k16, fp32 accum).
// Pixel tile: 32x8 per CTA; smem holds plane-pairs as half2.
template<int COUT, int L, bool GATES>
__global__ __launch_bounds__(256, 2)
void cell_mma(const float* __restrict__ x, long long x_bs,
              const float* __restrict__ in2,
              const uint4* __restrict__ wf,
              const float* __restrict__ bias,
              const float* __restrict__ hstate,
              float* __restrict__ out1,
              float* __restrict__ out2)
{
    constexpr int KTOT = (L == 0) ? 48 : 64;
    constexpr int PL2  = KTOT / 2;
    constexpr int KT16 = KTOT / 16;
    constexpr int MW   = COUT / 32;
    constexpr int NGRP = (COUT == 64) ? 4 : 8;   // warps along pixels
    constexpr int RPW  = 8 / NGRP;
    constexpr int N8   = RPW * 4;
    constexpr int MT   = 2;

    extern __shared__ uint Xs[];     // [PL2][10][36] half2 (plane pair per word)

    const int tid  = threadIdx.x;
    const int lane = tid & 31;
    const int wid  = tid >> 5;
    const int lq   = lane >> 2;      // 0..7
    const int lr   = lane & 3;       // 0..3
    const int nwarp = wid & (NGRP - 1);
    const int mwarp = wid / NGRP;
    const int pyw   = nwarp * RPW;

    const int b    = blockIdx.z;
    const int row0 = blockIdx.y * 8;
    const int col0 = blockIdx.x * 32;

    // ---- Stage plane pairs (zero halo), packed half2 ----
    for (int i = tid; i < PL2 * 340; i += 256) {
        const int pl2 = i / 340;
        const int rem = i - pl2 * 340;
        const int yy  = rem / 34;
        const int xx  = rem - yy * 34;
        const int gr = row0 + yy - 1, gc = col0 + xx - 1;
        const bool inb = (gr >= 0 && gr < HW && gc >= 0 && gc < HW);
        const int pix = gr * HW + gc;
        float v0 = 0.f, v1 = 0.f;
        if (inb) {
            const int p0 = 2 * pl2, p1 = 2 * pl2 + 1;
            if (L == 0) {
                if (p0 == 0) v0 = x[(size_t)b * x_bs + pix];
                else if (p0 >= 16) v0 = in2[((size_t)b * 32 + p0 - 16) * HW2 + pix];
                if (p1 >= 16) v1 = in2[((size_t)b * 32 + p1 - 16) * HW2 + pix];
            } else {
                v0 = (p0 < 32) ? x[(size_t)b * x_bs + (size_t)p0 * HW2 + pix]
                               : in2[((size_t)b * 32 + p0 - 32) * HW2 + pix];
                v1 = (p1 < 32) ? x[(size_t)b * x_bs + (size_t)p1 * HW2 + pix]
                               : in2[((size_t)b * 32 + p1 - 32) * HW2 + pix];
            }
        }
        Xs[pl2 * 360 + yy * 36 + xx] = h2u(v0, v1);
    }
    __syncthreads();

    float acc[MT][N8][4];
    #pragma unroll
    for (int mt = 0; mt < MT; mt++)
        #pragma unroll
        for (int j = 0; j < N8; j++)
            #pragma unroll
            for (int q = 0; q < 4; q++) acc[mt][j][q] = 0.f;

    // ---- Main loop: 9 taps x KT16 k-slices ----
    #pragma unroll 1
    for (int tap = 0; tap < 9; tap++) {
        const int dy = tap / 3, dx = tap - dy * 3;
        #pragma unroll
        for (int ks = 0; ks < KT16; ks++) {
            const uint* xb = Xs + (ks * 8 + lr) * 360 + dy * 36 + dx + lq;
            uint bf[N8][2];
            #pragma unroll
            for (int j = 0; j < N8; j++) {
                const uint* p = xb + (pyw + (j >> 2)) * 36 + (j & 3) * 8;
                bf[j][0] = p[0];          // plane pairs lr   (k 0..7)
                bf[j][1] = p[4 * 360];    // plane pairs lr+4 (k 8..15)
            }
            const uint4* wbase = wf + (((tap * KT16 + ks) * MW + mwarp) * 2) * 32 + lane;
            #pragma unroll
            for (int mt = 0; mt < MT; mt++) {
                const uint4 a = __ldg(wbase + mt * 32);
                #pragma unroll
                for (int j = 0; j < N8; j++)
                    mma16(acc[mt][j], a.x, a.y, a.z, a.w, bf[j][0], bf[j][1]);
            }
        }
    }

    // ---- Epilogue ----
    #pragma unroll
    for (int mt = 0; mt < MT; mt++) {
        #pragma unroll
        for (int j = 0; j < N8; j++) {
            const int py = row0 + pyw + (j >> 2);
            const int px = col0 + (j & 3) * 8 + 2 * lr;
            const size_t pix = (size_t)py * HW + px;
            #pragma unroll
            for (int h2 = 0; h2 < 2; h2++) {
                const int cc = mwarp * 32 + mt * 16 + lq + h2 * 8;
                const float bv = __ldg(bias + cc);
                float v0 = acc[mt][j][h2 * 2 + 0] + bv;
                float v1 = acc[mt][j][h2 * 2 + 1] + bv;
                if (GATES) {
                    const float g0 = sigf(v0), g1 = sigf(v1);
                    if (mwarp == 0) {   // r gate -> rh = r*h
                        const size_t off = ((size_t)b * 32 + cc) * HW2 + pix;
                        const float2 hv = *(const float2*)(hstate + off);
                        *(float2*)(out1 + off) = make_float2(g0 * hv.x, g1 * hv.y);
                    } else {            // z gate
                        const size_t off = ((size_t)b * 32 + cc - 32) * HW2 + pix;
                        *(float2*)(out2 + off) = make_float2(g0, g1);
                    }
                } else {
                    const size_t off = ((size_t)b * 32 + cc) * HW2 + pix;
                    const float2 zv = *(const float2*)(out2 + off);
                    const float2 hv = *(const float2*)(hstate + off);
                    const float n0 = tanhfast(v0), n1 = tanhfast(v1);
                    *(float2*)(out1 + off) =
                        make_float2(hv.x + zv.x * (n0 - hv.x),
                                    hv.y + zv.y * (n1 - hv.y));
                }
            }
        }
    }
}

extern "C" void kernel_launch(void* const* d_in, const int* in_sizes, int n_in,
                              void* d_out, int out_size)
{
    const float* seq = (const float*)d_in[0];
    const float* gw0 = (const float*)d_in[1];
    const float* gb0 = (const float*)d_in[2];
    const float* cw0 = (const float*)d_in[3];
    const float* cb0 = (const float*)d_in[4];
    const float* gw1 = (const float*)d_in[5];
    const float* gb1 = (const float*)d_in[6];
    const float* cw1 = (const float*)d_in[7];
    const float* cb1 = (const float*)d_in[8];

    float *h0, *h1, *rh, *zb;
    cudaGetSymbolAddress((void**)&h0, g_h0);
    cudaGetSymbolAddress((void**)&h1, g_h1);
    cudaGetSymbolAddress((void**)&rh, g_rh);
    cudaGetSymbolAddress((void**)&zb, g_z);
    uint4 *wfg0, *wfc0, *wfg1, *wfc1;
    cudaGetSymbolAddress((void**)&wfg0, g_wf_g0);
    cudaGetSymbolAddress((void**)&wfc0, g_wf_c0);
    cudaGetSymbolAddress((void**)&wfg1, g_wf_g1);
    cudaGetSymbolAddress((void**)&wfc1, g_wf_c1);

    const int SM0 = 24 * 360 * 4;   // 34560 B
    const int SM1 = 32 * 360 * 4;   // 46080 B

    zero_states_kernel<<<4096, 256>>>();
    prep_w<48, 64, 33, true ><<<(9*3*2*2*32 + 255)/256, 256>>>(gw0, wfg0);
    prep_w<48, 32, 33, true ><<<(9*3*1*2*32 + 255)/256, 256>>>(cw0, wfc0);
    prep_w<64, 64, 64, false><<<(9*4*2*2*32 + 255)/256, 256>>>(gw1, wfg1);
    prep_w<64, 32, 64, false><<<(9*4*1*2*32 + 255)/256, 256>>>(cw1, wfc1);

    dim3 grid(HW / 32, HW / 8, NB);  // (4, 16, 8)
    dim3 blk(256);
    const long long seq_bs = (long long)NT * HW2;
    const long long h_bs   = (long long)32 * HW2;

    for (int t = 0; t < NT; t++) {
        const float* xt = seq + (size_t)t * HW2;
        // Layer 0
        cell_mma<64, 0, true ><<<grid, blk, SM0>>>(xt, seq_bs, h0, wfg0, gb0, h0, rh, zb);
        cell_mma<32, 0, false><<<grid, blk, SM0>>>(xt, seq_bs, rh, wfc0, cb0, h0, h0, zb);
        // Layer 1
        cell_mma<64, 1, true ><<<grid, blk, SM1>>>(h0, h_bs, h1, wfg1, gb1, h1, rh, zb);
        float* hout = (t == NT - 1) ? (float*)d_out : h1;
        cell_mma<32, 1, false><<<grid, blk, SM1>>>(h0, h_bs, rh, wfc1, cb1, h1, hout, zb);
    }
}

// round 6
// speedup vs baseline: 5.4475x; 1.2272x over previous
#include <cuda_runtime.h>
#include <cuda_fp16.h>
#include <math.h>

#define HW   128
#define HW2  (128*128)
#define NB   8
#define NT   16
#define PSTR 408    // smem plane-pair stride (words): 10*40 + 8 -> conflict-free
#define RSTR 40     // smem row stride (words)

typedef unsigned int uint;

// fp32 state (blend precision) + z scratch
__device__ float g_h0[NB*32*HW2];
__device__ float g_h1[NB*32*HW2];
__device__ float g_z [NB*32*HW2];
// packed half2 plane-pair mirrors [b][16][HW2]: (ch 2q, ch 2q+1)
__device__ uint g_hp0[NB*16*HW2];
__device__ uint g_hp1[NB*16*HW2];
__device__ uint g_rhp[NB*16*HW2];

// Pre-swizzled weight fragments (f16x2, m16n8k16 A layout)
__device__ uint4 g_wf_g0[9 * 3 * 2 * 2 * 32];
__device__ uint4 g_wf_c0[9 * 3 * 1 * 2 * 32];
__device__ uint4 g_wf_g1[9 * 4 * 2 * 2 * 32];
__device__ uint4 g_wf_c1[9 * 4 * 1 * 2 * 32];

__global__ void zero_states_kernel() {
    size_t i = (size_t)blockIdx.x * blockDim.x + threadIdx.x;   // 1,048,576 threads
    float4 z4 = make_float4(0.f, 0.f, 0.f, 0.f);
    ((float4*)g_h0)[i] = z4;
    ((float4*)g_h1)[i] = z4;
    if (i < NB*16*HW2/4) {
        uint4 u4 = make_uint4(0, 0, 0, 0);
        ((uint4*)g_hp0)[i] = u4;
        ((uint4*)g_hp1)[i] = u4;
    }
}

__device__ __forceinline__ float sigf(float v) {
    return 1.0f / (1.0f + __expf(-v));
}
__device__ __forceinline__ float tanhfast(float v) {
    return 1.0f - 2.0f / (__expf(2.0f * v) + 1.0f);
}
__device__ __forceinline__ uint h2u(float lo, float hi) {
    __half2 h = __halves2half2(__float2half_rn(lo), __float2half_rn(hi));
    return *(uint*)&h;
}
__device__ __forceinline__ void mma16(float* c, uint a0, uint a1, uint a2, uint a3,
                                      uint b0, uint b1) {
    asm volatile(
        "mma.sync.aligned.m16n8k16.row.col.f32.f16.f16.f32 "
        "{%0,%1,%2,%3},{%4,%5,%6,%7},{%8,%9},{%0,%1,%2,%3};"
        : "+f"(c[0]), "+f"(c[1]), "+f"(c[2]), "+f"(c[3])
        : "r"(a0), "r"(a1), "r"(a2), "r"(a3), "r"(b0), "r"(b1));
}

// Virtual plane k -> weight cin.
// L0: k==0 -> x (cw 0); 2<=k<34 -> h (cw k-1); else zero-pad.  (pl2 0=(x,0), 1..16=h pairs)
// L1: k -> k.
template<int KTOT, int COUT, int CIN_W, bool L0>
__global__ void prep_w(const float* __restrict__ w, uint4* __restrict__ out) {
    constexpr int KT16 = KTOT / 16;
    constexpr int MW   = COUT / 32;
    const int total = 9 * KT16 * MW * 2 * 32;
    int idx = blockIdx.x * blockDim.x + threadIdx.x;
    if (idx >= total) return;
    int t = idx;
    const int lane = t & 31; t >>= 5;
    const int mt = t & 1; t >>= 1;
    const int mw = t % MW; t /= MW;
    const int ks = t % KT16;
    const int tap = t / KT16;

    const int co0 = mw * 32 + mt * 16 + (lane >> 2);
    const int kb  = ks * 16 + (lane & 3) * 2;

    auto Wv = [&](int co, int k) -> float {
        int cw;
        if (L0) cw = (k == 0) ? 0 : ((k >= 2 && k < 34) ? k - 1 : -1);
        else    cw = k;
        if (cw < 0) return 0.f;
        return w[((size_t)co * CIN_W + cw) * 9 + tap];
    };
    uint4 o;
    o.x = h2u(Wv(co0,     kb),     Wv(co0,     kb + 1));
    o.y = h2u(Wv(co0 + 8, kb),     Wv(co0 + 8, kb + 1));
    o.z = h2u(Wv(co0,     kb + 8), Wv(co0,     kb + 9));
    o.w = h2u(Wv(co0 + 8, kb + 8), Wv(co0 + 8, kb + 9));
    out[idx] = o;
}

// Implicit-GEMM ConvGRU half-cell, fp16 MMA, packed-mirror staging.
// Stage region: 10 rows x 40 cols (global rows row0-1.., cols col0-4..col0+35).
template<int COUT, int L, bool GATES>
__global__ __launch_bounds__(256, 2)
void cell_mma(const float* __restrict__ x, long long x_bs,
              const uint* __restrict__ mirA,   // L1: planes 0..15
              const uint* __restrict__ mirB,   // L1: planes 16..31 ; L0: planes 1..16
              const uint4* __restrict__ wf,
              const float* __restrict__ bias,
              const float* __restrict__ hstate,
              float* __restrict__ zbuf,        // GATES: write ; else read
              float* __restrict__ hout,        // !GATES: fp32 h out
              uint* __restrict__ outP)         // packed out (rh or h mirror)
{
    constexpr int NPL2 = (L == 0) ? 24 : 32;
    constexpr int KT16 = (L == 0) ? 3 : 4;
    constexpr int MW   = COUT / 32;
    constexpr int NGRP = (COUT == 64) ? 4 : 8;
    constexpr int RPW  = 8 / NGRP;
    constexpr int N8   = RPW * 4;
    constexpr int MT   = 2;

    extern __shared__ uint Xs[];     // [NPL2][10][40] half2, plane stride PSTR

    const int tid  = threadIdx.x;
    const int lane = tid & 31;
    const int wid  = tid >> 5;
    const int lq   = lane >> 2;
    const int lr   = lane & 3;
    const int nwarp = wid & (NGRP - 1);
    const int mwarp = wid / NGRP;
    const int pyw   = nwarp * RPW;

    const int b    = blockIdx.z;
    const int row0 = blockIdx.y * 8;
    const int col0 = blockIdx.x * 32;

    // ---- Stage: uint4 copy from packed mirrors (zero halo) ----
    for (int i = tid; i < NPL2 * 100; i += 256) {
        const int pl2 = i / 100;
        const int rem = i - pl2 * 100;
        const int yy  = rem / 10;
        const int s   = rem - yy * 10;
        const int gr  = row0 + yy - 1;
        const int gcb = col0 - 4 + s * 4;
        const bool ok = (gr >= 0 && gr < HW && gcb >= 0 && gcb < HW);
        uint4 v = make_uint4(0, 0, 0, 0);
        if (ok) {
            const int pix = gr * HW + gcb;
            if (L == 0) {
                if (pl2 == 0) {
                    const float4 f = *(const float4*)(x + (size_t)b * x_bs + pix);
                    v.x = h2u(f.x, 0.f); v.y = h2u(f.y, 0.f);
                    v.z = h2u(f.z, 0.f); v.w = h2u(f.w, 0.f);
                } else if (pl2 <= 16) {
                    v = *(const uint4*)(mirB + ((size_t)b * 16 + pl2 - 1) * HW2 + pix);
                }
            } else {
                const uint* src = (pl2 < 16)
                    ? mirA + ((size_t)b * 16 + pl2) * HW2
                    : mirB + ((size_t)b * 16 + pl2 - 16) * HW2;
                v = *(const uint4*)(src + pix);
            }
        }
        *(uint4*)(Xs + pl2 * PSTR + yy * RSTR + s * 4) = v;
    }
    __syncthreads();

    float acc[MT][N8][4];
    #pragma unroll
    for (int mt = 0; mt < MT; mt++)
        #pragma unroll
        for (int j = 0; j < N8; j++)
            #pragma unroll
            for (int q = 0; q < 4; q++) acc[mt][j][q] = 0.f;

    // ---- Main loop: 9 taps x KT16 slices ----
    #pragma unroll 1
    for (int tap = 0; tap < 9; tap++) {
        const int dy = tap / 3, dx = tap - dy * 3;
        #pragma unroll
        for (int ks = 0; ks < KT16; ks++) {
            const uint* xb = Xs + (ks * 8 + lr) * PSTR + dy * RSTR + dx + 3 + lq;
            uint bf[N8][2];
            #pragma unroll
            for (int j = 0; j < N8; j++) {
                const uint* p = xb + (pyw + (j >> 2)) * RSTR + (j & 3) * 8;
                bf[j][0] = p[0];
                bf[j][1] = p[4 * PSTR];
            }
            const uint4* wbase = wf + (((tap * KT16 + ks) * MW + mwarp) * 2) * 32 + lane;
            #pragma unroll
            for (int mt = 0; mt < MT; mt++) {
                const uint4 a = __ldg(wbase + mt * 32);
                #pragma unroll
                for (int j = 0; j < N8; j++)
                    mma16(acc[mt][j], a.x, a.y, a.z, a.w, bf[j][0], bf[j][1]);
            }
        }
    }

    // ---- Epilogue ----
    #pragma unroll
    for (int mt = 0; mt < MT; mt++) {
        #pragma unroll
        for (int j = 0; j < N8; j++) {
            const int py = row0 + pyw + (j >> 2);
            const int px = col0 + (j & 3) * 8 + 2 * lr;
            const size_t pix = (size_t)py * HW + px;
            #pragma unroll
            for (int h2 = 0; h2 < 2; h2++) {
                const int cc = mwarp * 32 + mt * 16 + lq + h2 * 8;
                const float bv = __ldg(bias + cc);
                float v0 = acc[mt][j][h2 * 2 + 0] + bv;
                float v1 = acc[mt][j][h2 * 2 + 1] + bv;
                if (GATES) {
                    if (mwarp == 0) {   // r gate -> packed rh mirror
                        const size_t off = ((size_t)b * 32 + cc) * HW2 + pix;
                        const float2 hv = *(const float2*)(hstate + off);
                        const float r0 = sigf(v0) * hv.x;
                        const float r1 = sigf(v1) * hv.y;
                        const float r0p = __shfl_xor_sync(0xffffffffu, r0, 4);
                        const float r1p = __shfl_xor_sync(0xffffffffu, r1, 4);
                        if (!(lq & 1)) {
                            uint2 wv;
                            wv.x = h2u(r0, r0p);
                            wv.y = h2u(r1, r1p);
                            *(uint2*)(outP + ((size_t)b * 16 + (cc >> 1)) * HW2 + pix) = wv;
                        }
                    } else {            // z gate -> fp32 planes
                        const size_t off = ((size_t)b * 32 + cc - 32) * HW2 + pix;
                        *(float2*)(zbuf + off) = make_float2(sigf(v0), sigf(v1));
                    }
                } else {
                    const size_t off = ((size_t)b * 32 + cc) * HW2 + pix;
                    const float2 zv = *(const float2*)(zbuf + off);
                    const float2 hv = *(const float2*)(hstate + off);
                    const float n0 = tanhfast(v0), n1 = tanhfast(v1);
                    const float o0 = hv.x + zv.x * (n0 - hv.x);
                    const float o1 = hv.y + zv.y * (n1 - hv.y);
                    *(float2*)(hout + off) = make_float2(o0, o1);
                    const float o0p = __shfl_xor_sync(0xffffffffu, o0, 4);
                    const float o1p = __shfl_xor_sync(0xffffffffu, o1, 4);
                    if (!(lq & 1)) {
                        uint2 wv;
                        wv.x = h2u(o0, o0p);
                        wv.y = h2u(o1, o1p);
                        *(uint2*)(outP + ((size_t)b * 16 + (cc >> 1)) * HW2 + pix) = wv;
                    }
                }
            }
        }
    }
}

extern "C" void kernel_launch(void* const* d_in, const int* in_sizes, int n_in,
                              void* d_out, int out_size)
{
    const float* seq = (const float*)d_in[0];
    const float* gw0 = (const float*)d_in[1];
    const float* gb0 = (const float*)d_in[2];
    const float* cw0 = (const float*)d_in[3];
    const float* cb0 = (const float*)d_in[4];
    const float* gw1 = (const float*)d_in[5];
    const float* gb1 = (const float*)d_in[6];
    const float* cw1 = (const float*)d_in[7];
    const float* cb1 = (const float*)d_in[8];

    float *h0, *h1, *zb;
    uint *hp0, *hp1, *rhp;
    cudaGetSymbolAddress((void**)&h0, g_h0);
    cudaGetSymbolAddress((void**)&h1, g_h1);
    cudaGetSymbolAddress((void**)&zb, g_z);
    cudaGetSymbolAddress((void**)&hp0, g_hp0);
    cudaGetSymbolAddress((void**)&hp1, g_hp1);
    cudaGetSymbolAddress((void**)&rhp, g_rhp);
    uint4 *wfg0, *wfc0, *wfg1, *wfc1;
    cudaGetSymbolAddress((void**)&wfg0, g_wf_g0);
    cudaGetSymbolAddress((void**)&wfc0, g_wf_c0);
    cudaGetSymbolAddress((void**)&wfg1, g_wf_g1);
    cudaGetSymbolAddress((void**)&wfc1, g_wf_c1);

    const int SM0 = 24 * PSTR * 4;   // 39168 B
    const int SM1 = 32 * PSTR * 4;   // 52224 B
    cudaFuncSetAttribute(cell_mma<64, 0, true >, cudaFuncAttributeMaxDynamicSharedMemorySize, SM0);
    cudaFuncSetAttribute(cell_mma<32, 0, false>, cudaFuncAttributeMaxDynamicSharedMemorySize, SM0);
    cudaFuncSetAttribute(cell_mma<64, 1, true >, cudaFuncAttributeMaxDynamicSharedMemorySize, SM1);
    cudaFuncSetAttribute(cell_mma<32, 1, false>, cudaFuncAttributeMaxDynamicSharedMemorySize, SM1);

    zero_states_kernel<<<4096, 256>>>();
    prep_w<48, 64, 33, true ><<<(9*3*2*2*32 + 255)/256, 256>>>(gw0, wfg0);
    prep_w<48, 32, 33, true ><<<(9*3*1*2*32 + 255)/256, 256>>>(cw0, wfc0);
    prep_w<64, 64, 64, false><<<(9*4*2*2*32 + 255)/256, 256>>>(gw1, wfg1);
    prep_w<64, 32, 64, false><<<(9*4*1*2*32 + 255)/256, 256>>>(cw1, wfc1);

    dim3 grid(HW / 32, HW / 8, NB);  // (4, 16, 8)
    dim3 blk(256);
    const long long seq_bs = (long long)NT * HW2;

    for (int t = 0; t < NT; t++) {
        const float* xt = seq + (size_t)t * HW2;
        // Layer 0 (x = seq frame, h = h0)
        cell_mma<64, 0, true ><<<grid, blk, SM0>>>(xt, seq_bs, hp0, hp0, wfg0, gb0,
                                                   h0, zb, h0, rhp);
        cell_mma<32, 0, false><<<grid, blk, SM0>>>(xt, seq_bs, rhp, rhp, wfc0, cb0,
                                                   h0, zb, h0, hp0);
        // Layer 1 (x = h0, h = h1)
        cell_mma<64, 1, true ><<<grid, blk, SM1>>>(nullptr, 0, hp0, hp1, wfg1, gb1,
                                                   h1, zb, h1, rhp);
        float* hout = (t == NT - 1) ? (float*)d_out : h1;
        cell_mma<32, 1, false><<<grid, blk, SM1>>>(nullptr, 0, hp0, rhp, wfc1, cb1,
                                                   h1, zb, hout, hp1);
    }
}